// round 1
// baseline (speedup 1.0000x reference)
#include <cuda_runtime.h>

#define B_  2
#define T_  2048
#define C_  1024
#define H_  16
#define DH_ 64
#define M_  (B_ * T_)   // 4096

// Static device scratch for Q/K/V projections, each [B,T,C] fp32 (16.8 MB each).
__device__ float g_q[M_ * C_];
__device__ float g_k[M_ * C_];
__device__ float g_v[M_ * C_];

// ---------------------------------------------------------------------------
// QKV projection: Out = X[4096,1024] @ W[1024,1024] + b, blockIdx.z selects Q/K/V
// 128x128x16 tile, 256 threads, 8x8 micro-tile per thread.
// ---------------------------------------------------------------------------
__global__ __launch_bounds__(256)
void qkv_gemm(const float* __restrict__ x,
              const float* __restrict__ Wq, const float* __restrict__ bq,
              const float* __restrict__ Wk, const float* __restrict__ bk,
              const float* __restrict__ Wv, const float* __restrict__ bv)
{
    const int which = blockIdx.z;
    const float* __restrict__ W    = (which == 0) ? Wq : (which == 1) ? Wk : Wv;
    const float* __restrict__ bias = (which == 0) ? bq : (which == 1) ? bk : bv;
    float* __restrict__ out        = (which == 0) ? g_q : (which == 1) ? g_k : g_v;

    __shared__ float As[16 * 128];   // transposed: As[k][m]
    __shared__ float Bs[16 * 128];   // Bs[k][n]

    const int tid = threadIdx.x;
    const int tx  = tid & 15;
    const int ty  = tid >> 4;
    const int m0  = blockIdx.y * 128;
    const int n0  = blockIdx.x * 128;

    float acc[8][8];
#pragma unroll
    for (int i = 0; i < 8; i++)
#pragma unroll
        for (int j = 0; j < 8; j++) acc[i][j] = 0.0f;

    for (int k0 = 0; k0 < C_; k0 += 16) {
        // Load A tile 128x16 (transpose into As)
#pragma unroll
        for (int t = 0; t < 2; t++) {
            int id  = tid + t * 256;
            int row = id >> 2;
            int c4  = id & 3;
            float4 v = *(const float4*)&x[(size_t)(m0 + row) * C_ + k0 + c4 * 4];
            As[(c4 * 4 + 0) * 128 + row] = v.x;
            As[(c4 * 4 + 1) * 128 + row] = v.y;
            As[(c4 * 4 + 2) * 128 + row] = v.z;
            As[(c4 * 4 + 3) * 128 + row] = v.w;
        }
        // Load B tile 16x128
#pragma unroll
        for (int t = 0; t < 2; t++) {
            int id  = tid + t * 256;
            int row = id >> 5;
            int c4  = id & 31;
            *(float4*)&Bs[row * 128 + c4 * 4] =
                *(const float4*)&W[(size_t)(k0 + row) * C_ + n0 + c4 * 4];
        }
        __syncthreads();

#pragma unroll
        for (int k = 0; k < 16; k++) {
            float a[8], b[8];
            *(float4*)&a[0] = *(const float4*)&As[k * 128 + ty * 8];
            *(float4*)&a[4] = *(const float4*)&As[k * 128 + ty * 8 + 4];
            *(float4*)&b[0] = *(const float4*)&Bs[k * 128 + tx * 8];
            *(float4*)&b[4] = *(const float4*)&Bs[k * 128 + tx * 8 + 4];
#pragma unroll
            for (int i = 0; i < 8; i++)
#pragma unroll
                for (int j = 0; j < 8; j++)
                    acc[i][j] = fmaf(a[i], b[j], acc[i][j]);
        }
        __syncthreads();
    }

    // Epilogue: add bias, write
#pragma unroll
    for (int i = 0; i < 8; i++) {
        size_t gr = (size_t)(m0 + ty * 8 + i) * C_;
#pragma unroll
        for (int j = 0; j < 8; j += 4) {
            int gc = n0 + tx * 8 + j;
            float4 o;
            o.x = acc[i][j + 0] + bias[gc + 0];
            o.y = acc[i][j + 1] + bias[gc + 1];
            o.z = acc[i][j + 2] + bias[gc + 2];
            o.w = acc[i][j + 3] + bias[gc + 3];
            *(float4*)&out[gr + gc] = o;
        }
    }
}

// ---------------------------------------------------------------------------
// Attention: flash-style. One block = one (b,h) x 64 query rows.
// 256 threads = 16x16 (ty=row-group, tx=col-group).
// Key-column ownership interleaved: thread tx owns keys {tx, tx+16, tx+32, tx+48}
// (lane stride 68 words = 4 banks -> conflict-free LDS.128 per phase).
// Dims in PV owned contiguously: c0 = 4*tx (float4 V loads / output stores).
// ---------------------------------------------------------------------------
#define PADW 68   // row stride in floats; 68*4 = 272 B, multiple of 16 (float4 ok)

__global__ __launch_bounds__(256)
void attn_kernel(const int* __restrict__ mask, float* __restrict__ y)
{
    extern __shared__ float sm[];
    float* Qs = sm;                     // [64][PADW]
    float* Ks = Qs + 64 * PADW;
    float* Vs = Ks + 64 * PADW;
    float* Ps = Vs + 64 * PADW;
    int*   km = (int*)(Ps + 64 * PADW); // [64]

    const int tid = threadIdx.x;
    const int tx  = tid & 15;
    const int ty  = tid >> 4;
    const int bh  = blockIdx.y;
    const int b   = bh >> 4;
    const int h   = bh & 15;
    const int q0  = blockIdx.x * 64;
    const int r0  = ty * 4;             // 4 query rows per thread
    const int c0  = tx * 4;             // 4 output dims per thread (PV phase)
    const size_t base = ((size_t)b * T_) * C_ + h * DH_;  // + t*C_ + d

    // Load Q tile (64 rows x 64 dims)
#pragma unroll
    for (int t = 0; t < 4; t++) {
        int id  = tid + t * 256;
        int row = id >> 4;
        int c4  = id & 15;
        *(float4*)&Qs[row * PADW + c4 * 4] =
            *(const float4*)&g_q[base + (size_t)(q0 + row) * C_ + c4 * 4];
    }
    int qm[4];
#pragma unroll
    for (int i = 0; i < 4; i++) qm[i] = mask[b * T_ + q0 + r0 + i];

    float  m_i[4], l_i[4];
    float4 accO[4];
#pragma unroll
    for (int i = 0; i < 4; i++) {
        m_i[i] = -1e30f;
        l_i[i] = 0.0f;
        accO[i] = make_float4(0.f, 0.f, 0.f, 0.f);
    }

    for (int kt = 0; kt < T_ / 64; kt++) {
        const int kb = kt * 64;
        // Load K and V tiles
#pragma unroll
        for (int t = 0; t < 4; t++) {
            int id  = tid + t * 256;
            int row = id >> 4;
            int c4  = id & 15;
            *(float4*)&Ks[row * PADW + c4 * 4] =
                *(const float4*)&g_k[base + (size_t)(kb + row) * C_ + c4 * 4];
            *(float4*)&Vs[row * PADW + c4 * 4] =
                *(const float4*)&g_v[base + (size_t)(kb + row) * C_ + c4 * 4];
        }
        if (tid < 64) km[tid] = mask[b * T_ + kb + tid];
        __syncthreads();

        // S = Q K^T * 0.125 for this thread's 4 rows x 4 (interleaved) key cols
        float s[4][4];
#pragma unroll
        for (int i = 0; i < 4; i++)
#pragma unroll
            for (int j = 0; j < 4; j++) s[i][j] = 0.0f;

#pragma unroll
        for (int d4 = 0; d4 < 16; d4++) {
            float4 qv[4], kv[4];
#pragma unroll
            for (int i = 0; i < 4; i++)
                qv[i] = *(const float4*)&Qs[(r0 + i) * PADW + d4 * 4];
#pragma unroll
            for (int j = 0; j < 4; j++)
                kv[j] = *(const float4*)&Ks[(tx + 16 * j) * PADW + d4 * 4];
#pragma unroll
            for (int i = 0; i < 4; i++)
#pragma unroll
                for (int j = 0; j < 4; j++) {
                    s[i][j] = fmaf(qv[i].x, kv[j].x, s[i][j]);
                    s[i][j] = fmaf(qv[i].y, kv[j].y, s[i][j]);
                    s[i][j] = fmaf(qv[i].z, kv[j].z, s[i][j]);
                    s[i][j] = fmaf(qv[i].w, kv[j].w, s[i][j]);
                }
        }

        int kvj[4];
#pragma unroll
        for (int j = 0; j < 4; j++) kvj[j] = km[tx + 16 * j];

        // Online softmax per row (16-lane groups align with warp halves)
#pragma unroll
        for (int i = 0; i < 4; i++) {
            float tm = -1e30f;
#pragma unroll
            for (int j = 0; j < 4; j++) {
                s[i][j] = kvj[j] ? s[i][j] * 0.125f : -1e30f;
                tm = fmaxf(tm, s[i][j]);
            }
#pragma unroll
            for (int off = 8; off > 0; off >>= 1)
                tm = fmaxf(tm, __shfl_xor_sync(0xffffffffu, tm, off));

            float newm  = fmaxf(m_i[i], tm);
            float alpha = __expf(m_i[i] - newm);
            float p[4];
            float sum = 0.0f;
#pragma unroll
            for (int j = 0; j < 4; j++) {
                p[j] = (s[i][j] > -1e29f) ? __expf(s[i][j] - newm) : 0.0f;
                sum += p[j];
            }
#pragma unroll
            for (int off = 8; off > 0; off >>= 1)
                sum += __shfl_xor_sync(0xffffffffu, sum, off);

            l_i[i] = l_i[i] * alpha + sum;
            m_i[i] = newm;
            accO[i].x *= alpha; accO[i].y *= alpha;
            accO[i].z *= alpha; accO[i].w *= alpha;
#pragma unroll
            for (int j = 0; j < 4; j++)
                Ps[(r0 + i) * PADW + tx + 16 * j] = p[j];
        }
        __syncthreads();

        // O += P @ V  (rows r0.., dims c0..c0+3)
#pragma unroll
        for (int j4 = 0; j4 < 16; j4++) {
            float4 p[4];
#pragma unroll
            for (int i = 0; i < 4; i++)
                p[i] = *(const float4*)&Ps[(r0 + i) * PADW + j4 * 4];
            float4 v0 = *(const float4*)&Vs[(j4 * 4 + 0) * PADW + c0];
            float4 v1 = *(const float4*)&Vs[(j4 * 4 + 1) * PADW + c0];
            float4 v2 = *(const float4*)&Vs[(j4 * 4 + 2) * PADW + c0];
            float4 v3 = *(const float4*)&Vs[(j4 * 4 + 3) * PADW + c0];
#pragma unroll
            for (int i = 0; i < 4; i++) {
                accO[i].x += p[i].x * v0.x + p[i].y * v1.x + p[i].z * v2.x + p[i].w * v3.x;
                accO[i].y += p[i].x * v0.y + p[i].y * v1.y + p[i].z * v2.y + p[i].w * v3.y;
                accO[i].z += p[i].x * v0.z + p[i].y * v1.z + p[i].z * v2.z + p[i].w * v3.z;
                accO[i].w += p[i].x * v0.w + p[i].y * v1.w + p[i].z * v2.w + p[i].w * v3.w;
            }
        }
        __syncthreads();
    }

    // Normalize + write (masked query rows -> 0, matching reference)
#pragma unroll
    for (int i = 0; i < 4; i++) {
        float inv = (qm[i] != 0 && l_i[i] > 0.0f) ? (1.0f / l_i[i]) : 0.0f;
        float4 o = accO[i];
        o.x *= inv; o.y *= inv; o.z *= inv; o.w *= inv;
        *(float4*)&y[base + (size_t)(q0 + r0 + i) * C_ + c0] = o;
    }
}

// ---------------------------------------------------------------------------
extern "C" void kernel_launch(void* const* d_in, const int* in_sizes, int n_in,
                              void* d_out, int out_size)
{
    const float* x    = (const float*)d_in[0];
    const float* Wq   = (const float*)d_in[1];
    const float* bq   = (const float*)d_in[2];
    const float* Wk   = (const float*)d_in[3];
    const float* bk   = (const float*)d_in[4];
    const float* Wv   = (const float*)d_in[5];
    const float* bv   = (const float*)d_in[6];
    const int*   mask = (const int*)d_in[7];
    float*       y    = (float*)d_out;

    dim3 ggrid(C_ / 128, M_ / 128, 3);
    qkv_gemm<<<ggrid, 256>>>(x, Wq, bq, Wk, bk, Wv, bv);

    const int att_smem = (4 * 64 * PADW) * (int)sizeof(float) + 64 * (int)sizeof(int);
    cudaFuncSetAttribute(attn_kernel, cudaFuncAttributeMaxDynamicSharedMemorySize, att_smem);
    dim3 agrid(T_ / 64, B_ * H_);
    attn_kernel<<<agrid, 256, att_smem>>>(mask, y);
}

// round 3
// speedup vs baseline: 2.8169x; 2.8169x over previous
#include <cuda_runtime.h>
#include <cstdint>

#define B_  2
#define T_  2048
#define C_  1024
#define H_  16
#define DH_ 64
#define M_  (B_ * T_)   // 4096

// Static device scratch for Q/K/V projections (fp32)
__device__ float g_q[M_ * C_];
__device__ float g_k[M_ * C_];
__device__ float g_v[M_ * C_];

// ---------------------------------------------------------------------------
// Helpers: tf32 convert + m16n8k8 tf32 mma (family-portable, sm_80+)
// ---------------------------------------------------------------------------
__device__ __forceinline__ uint32_t f2tf32(float a) {
    uint32_t r;
    asm("cvt.rna.tf32.f32 %0, %1;" : "=r"(r) : "f"(a));
    return r;
}
__device__ __forceinline__ void mma_tf32(float* d, const uint32_t* a, const uint32_t* b) {
    asm volatile(
        "mma.sync.aligned.m16n8k8.row.col.f32.tf32.tf32.f32 "
        "{%0,%1,%2,%3}, {%4,%5,%6,%7}, {%8,%9}, {%0,%1,%2,%3};"
        : "+f"(d[0]), "+f"(d[1]), "+f"(d[2]), "+f"(d[3])
        : "r"(a[0]), "r"(a[1]), "r"(a[2]), "r"(a[3]), "r"(b[0]), "r"(b[1]));
}

// ---------------------------------------------------------------------------
// QKV projection: Out = X[4096,1024] @ W[1024,1024] + b  (blockIdx.z = q/k/v)
// 256 threads = 8 warps; CTA tile 128x128; warp tile 32m x 64n; K chunk 16.
// Xs stride 20 (A-frag bank: 20g+q distinct mod 32); Ws stride 136 (8q+g).
// ---------------------------------------------------------------------------
#define KC_   16
#define NCH_  (C_ / KC_)    // 64
#define XSTR  20
#define WSTR  136

__global__ __launch_bounds__(256, 2)
void qkv_gemm_mma(const float* __restrict__ x,
                  const float* __restrict__ Wq, const float* __restrict__ bq,
                  const float* __restrict__ Wk, const float* __restrict__ bk,
                  const float* __restrict__ Wv, const float* __restrict__ bv)
{
    __shared__ uint32_t Xs[2][128 * XSTR];
    __shared__ uint32_t Ws[2][KC_ * WSTR];

    const int which = blockIdx.z;
    const float* __restrict__ W    = (which == 0) ? Wq : (which == 1) ? Wk : Wv;
    const float* __restrict__ bias = (which == 0) ? bq : (which == 1) ? bk : bv;
    float* __restrict__ out        = (which == 0) ? g_q : (which == 1) ? g_k : g_v;

    const int tid    = threadIdx.x;
    const int wid    = tid >> 5;
    const int lane   = tid & 31;
    const int g      = lane >> 2;   // group id (row within fragment)
    const int q      = lane & 3;    // thread-in-group (col within fragment)
    const int warp_m = wid & 3;     // 0..3 -> 32-row slabs
    const int warp_n = wid >> 2;    // 0..1 -> 64-col slabs
    const int m0     = blockIdx.y * 128;
    const int n0     = blockIdx.x * 128;

    float d[2][8][4];
#pragma unroll
    for (int mt = 0; mt < 2; mt++)
#pragma unroll
        for (int nt = 0; nt < 8; nt++)
#pragma unroll
            for (int r = 0; r < 4; r++) d[mt][nt][r] = 0.0f;

    float4 px[2], pw[2];

    // prologue: load + store chunk 0
#pragma unroll
    for (int t = 0; t < 2; t++) {
        int idx = tid + t * 256;
        int row = idx >> 2, q4 = idx & 3;
        px[t] = *(const float4*)&x[(size_t)(m0 + row) * C_ + q4 * 4];
        int wr = idx >> 5, n4 = idx & 31;
        pw[t] = *(const float4*)&W[(size_t)wr * C_ + n0 + n4 * 4];
    }
#pragma unroll
    for (int t = 0; t < 2; t++) {
        int idx = tid + t * 256;
        int row = idx >> 2, q4 = idx & 3;
        uint32_t* px4 = &Xs[0][row * XSTR + q4 * 4];
        px4[0] = f2tf32(px[t].x); px4[1] = f2tf32(px[t].y);
        px4[2] = f2tf32(px[t].z); px4[3] = f2tf32(px[t].w);
        int wr = idx >> 5, n4 = idx & 31;
        uint32_t* pw4 = &Ws[0][wr * WSTR + n4 * 4];
        pw4[0] = f2tf32(pw[t].x); pw4[1] = f2tf32(pw[t].y);
        pw4[2] = f2tf32(pw[t].z); pw4[3] = f2tf32(pw[t].w);
    }
    __syncthreads();

    for (int kc = 0; kc < NCH_; kc++) {
        const int cur = kc & 1;
        // prefetch next chunk into registers
        if (kc + 1 < NCH_) {
            const int kb = (kc + 1) * KC_;
#pragma unroll
            for (int t = 0; t < 2; t++) {
                int idx = tid + t * 256;
                int row = idx >> 2, q4 = idx & 3;
                px[t] = *(const float4*)&x[(size_t)(m0 + row) * C_ + kb + q4 * 4];
                int wr = idx >> 5, n4 = idx & 31;
                pw[t] = *(const float4*)&W[(size_t)(kb + wr) * C_ + n0 + n4 * 4];
            }
        }
        // compute current chunk: 2 k-steps of 8
#pragma unroll
        for (int ks = 0; ks < 2; ks++) {
            const int k0 = ks * 8;
            uint32_t a[2][4];
#pragma unroll
            for (int mt = 0; mt < 2; mt++) {
                const int rm = warp_m * 32 + mt * 16;
                a[mt][0] = Xs[cur][(rm + g)     * XSTR + k0 + q];
                a[mt][1] = Xs[cur][(rm + g + 8) * XSTR + k0 + q];
                a[mt][2] = Xs[cur][(rm + g)     * XSTR + k0 + 4 + q];
                a[mt][3] = Xs[cur][(rm + g + 8) * XSTR + k0 + 4 + q];
            }
#pragma unroll
            for (int nt = 0; nt < 8; nt++) {
                const int cb = warp_n * 64 + nt * 8 + g;
                uint32_t b[2];
                b[0] = Ws[cur][(k0 + q)     * WSTR + cb];
                b[1] = Ws[cur][(k0 + 4 + q) * WSTR + cb];
                mma_tf32(d[0][nt], a[0], b);
                mma_tf32(d[1][nt], a[1], b);
            }
        }
        // store prefetched chunk into other buffer
        if (kc + 1 < NCH_) {
            const int nb = cur ^ 1;
#pragma unroll
            for (int t = 0; t < 2; t++) {
                int idx = tid + t * 256;
                int row = idx >> 2, q4 = idx & 3;
                uint32_t* px4 = &Xs[nb][row * XSTR + q4 * 4];
                px4[0] = f2tf32(px[t].x); px4[1] = f2tf32(px[t].y);
                px4[2] = f2tf32(px[t].z); px4[3] = f2tf32(px[t].w);
                int wr = idx >> 5, n4 = idx & 31;
                uint32_t* pw4 = &Ws[nb][wr * WSTR + n4 * 4];
                pw4[0] = f2tf32(pw[t].x); pw4[1] = f2tf32(pw[t].y);
                pw4[2] = f2tf32(pw[t].z); pw4[3] = f2tf32(pw[t].w);
            }
        }
        __syncthreads();
    }

    // epilogue: bias + store
#pragma unroll
    for (int mt = 0; mt < 2; mt++) {
        const int rw = m0 + warp_m * 32 + mt * 16 + g;
#pragma unroll
        for (int nt = 0; nt < 8; nt++) {
            const int cc = n0 + warp_n * 64 + nt * 8 + 2 * q;
            const float b0 = bias[cc], b1 = bias[cc + 1];
            float2 v0 = make_float2(d[mt][nt][0] + b0, d[mt][nt][1] + b1);
            float2 v1 = make_float2(d[mt][nt][2] + b0, d[mt][nt][3] + b1);
            *(float2*)&out[(size_t)rw * C_ + cc]       = v0;
            *(float2*)&out[(size_t)(rw + 8) * C_ + cc] = v1;
        }
    }
}

// ---------------------------------------------------------------------------
// Attention (flash-style) on mma.sync tf32.
// 256 threads = 8 warps; CTA = 128 query rows (warp w -> rows 16w..16w+15),
// key tile 64. S and O accumulate in C-fragments; softmax on fragment layout
// (quad-lane shuffles); P staged via smem (warp-private rows -> __syncwarp).
// Strides chosen for conflict-free fragment LDS: Qs/Ks/Ps 68, Vs 72.
// ---------------------------------------------------------------------------
#define SQ 68
#define SK 68
#define SV 72
#define SP 68
#define ATT_SMEM_WORDS (128 * SQ + 64 * SK + 64 * SV + 128 * SP + 64)

__global__ __launch_bounds__(256, 2)
void attn_mma(const int* __restrict__ mask, float* __restrict__ y)
{
    extern __shared__ uint32_t smu[];
    uint32_t* Qs = smu;
    uint32_t* Ks = Qs + 128 * SQ;
    uint32_t* Vs = Ks + 64 * SK;
    uint32_t* Ps = Vs + 64 * SV;
    int*      km = (int*)(Ps + 128 * SP);

    const int tid  = threadIdx.x;
    const int wid  = tid >> 5;
    const int lane = tid & 31;
    const int g    = lane >> 2;
    const int q    = lane & 3;
    const int w16  = wid * 16;
    const int bh   = blockIdx.y;
    const int b    = bh >> 4;
    const int h    = bh & 15;
    const int q0   = blockIdx.x * 128;
    const size_t base = ((size_t)b * T_) * C_ + h * DH_;

    // load Q tile (128 rows x 64 dims), tf32-rounded
#pragma unroll
    for (int t = 0; t < 8; t++) {
        int idx = tid + t * 256;
        int row = idx >> 4, c4 = idx & 15;
        float4 v = *(const float4*)&g_q[base + (size_t)(q0 + row) * C_ + c4 * 4];
        uint32_t* p = &Qs[row * SQ + c4 * 4];
        p[0] = f2tf32(v.x); p[1] = f2tf32(v.y); p[2] = f2tf32(v.z); p[3] = f2tf32(v.w);
    }

    float o[8][4];
#pragma unroll
    for (int dt = 0; dt < 8; dt++)
#pragma unroll
        for (int r = 0; r < 4; r++) o[dt][r] = 0.0f;
    float m_lo = -1e30f, m_hi = -1e30f, l_lo = 0.0f, l_hi = 0.0f;

    for (int kt = 0; kt < T_ / 64; kt++) {
        const int kb = kt * 64;
        __syncthreads();   // previous tile's PV reads done
        // stage K, V (tf32), key mask
#pragma unroll
        for (int t = 0; t < 4; t++) {
            int idx = tid + t * 256;
            int row = idx >> 4, c4 = idx & 15;
            float4 kv = *(const float4*)&g_k[base + (size_t)(kb + row) * C_ + c4 * 4];
            float4 vv = *(const float4*)&g_v[base + (size_t)(kb + row) * C_ + c4 * 4];
            uint32_t* pk = &Ks[row * SK + c4 * 4];
            pk[0] = f2tf32(kv.x); pk[1] = f2tf32(kv.y); pk[2] = f2tf32(kv.z); pk[3] = f2tf32(kv.w);
            uint32_t* pv = &Vs[row * SV + c4 * 4];
            pv[0] = f2tf32(vv.x); pv[1] = f2tf32(vv.y); pv[2] = f2tf32(vv.z); pv[3] = f2tf32(vv.w);
        }
        if (tid < 64) km[tid] = mask[b * T_ + kb + tid];
        __syncthreads();

        // S = Q K^T  (warp rows w16..w16+15, 64 key cols)
        float s[8][4];
#pragma unroll
        for (int nt = 0; nt < 8; nt++)
#pragma unroll
            for (int r = 0; r < 4; r++) s[nt][r] = 0.0f;

#pragma unroll
        for (int ks = 0; ks < 8; ks++) {
            const int k0 = ks * 8;
            uint32_t a[4];
            a[0] = Qs[(w16 + g)     * SQ + k0 + q];
            a[1] = Qs[(w16 + g + 8) * SQ + k0 + q];
            a[2] = Qs[(w16 + g)     * SQ + k0 + 4 + q];
            a[3] = Qs[(w16 + g + 8) * SQ + k0 + 4 + q];
#pragma unroll
            for (int nt = 0; nt < 8; nt++) {
                uint32_t bfr[2];
                bfr[0] = Ks[(nt * 8 + g) * SK + k0 + q];
                bfr[1] = Ks[(nt * 8 + g) * SK + k0 + 4 + q];
                mma_tf32(s[nt], a, bfr);
            }
        }

        // masked online softmax on the C-fragment layout
        float tlo = -1e30f, thi = -1e30f;
#pragma unroll
        for (int nt = 0; nt < 8; nt++) {
            const int c = nt * 8 + 2 * q;
            const int k0v = km[c], k1v = km[c + 1];
            s[nt][0] = k0v ? s[nt][0] * 0.125f : -1e30f;
            s[nt][1] = k1v ? s[nt][1] * 0.125f : -1e30f;
            s[nt][2] = k0v ? s[nt][2] * 0.125f : -1e30f;
            s[nt][3] = k1v ? s[nt][3] * 0.125f : -1e30f;
            tlo = fmaxf(tlo, fmaxf(s[nt][0], s[nt][1]));
            thi = fmaxf(thi, fmaxf(s[nt][2], s[nt][3]));
        }
        tlo = fmaxf(tlo, __shfl_xor_sync(0xffffffffu, tlo, 1));
        tlo = fmaxf(tlo, __shfl_xor_sync(0xffffffffu, tlo, 2));
        thi = fmaxf(thi, __shfl_xor_sync(0xffffffffu, thi, 1));
        thi = fmaxf(thi, __shfl_xor_sync(0xffffffffu, thi, 2));

        const float nm_lo = fmaxf(m_lo, tlo);
        const float nm_hi = fmaxf(m_hi, thi);
        const float al_lo = __expf(m_lo - nm_lo);
        const float al_hi = __expf(m_hi - nm_hi);

        float suml = 0.0f, sumh = 0.0f;
#pragma unroll
        for (int nt = 0; nt < 8; nt++) {
            float p0 = (s[nt][0] > -1e29f) ? __expf(s[nt][0] - nm_lo) : 0.0f;
            float p1 = (s[nt][1] > -1e29f) ? __expf(s[nt][1] - nm_lo) : 0.0f;
            float p2 = (s[nt][2] > -1e29f) ? __expf(s[nt][2] - nm_hi) : 0.0f;
            float p3 = (s[nt][3] > -1e29f) ? __expf(s[nt][3] - nm_hi) : 0.0f;
            suml += p0 + p1;
            sumh += p2 + p3;
            const int c = nt * 8 + 2 * q;
            Ps[(w16 + g)     * SP + c]     = f2tf32(p0);
            Ps[(w16 + g)     * SP + c + 1] = f2tf32(p1);
            Ps[(w16 + g + 8) * SP + c]     = f2tf32(p2);
            Ps[(w16 + g + 8) * SP + c + 1] = f2tf32(p3);
        }
        suml += __shfl_xor_sync(0xffffffffu, suml, 1);
        suml += __shfl_xor_sync(0xffffffffu, suml, 2);
        sumh += __shfl_xor_sync(0xffffffffu, sumh, 1);
        sumh += __shfl_xor_sync(0xffffffffu, sumh, 2);

        l_lo = l_lo * al_lo + suml;  m_lo = nm_lo;
        l_hi = l_hi * al_hi + sumh;  m_hi = nm_hi;
#pragma unroll
        for (int dt = 0; dt < 8; dt++) {
            o[dt][0] *= al_lo; o[dt][1] *= al_lo;
            o[dt][2] *= al_hi; o[dt][3] *= al_hi;
        }
        __syncwarp();

        // O += P @ V
#pragma unroll
        for (int ks = 0; ks < 8; ks++) {
            const int k0 = ks * 8;
            uint32_t a[4];
            a[0] = Ps[(w16 + g)     * SP + k0 + q];
            a[1] = Ps[(w16 + g + 8) * SP + k0 + q];
            a[2] = Ps[(w16 + g)     * SP + k0 + 4 + q];
            a[3] = Ps[(w16 + g + 8) * SP + k0 + 4 + q];
#pragma unroll
            for (int dt = 0; dt < 8; dt++) {
                uint32_t bfr[2];
                bfr[0] = Vs[(k0 + q)     * SV + dt * 8 + g];
                bfr[1] = Vs[(k0 + 4 + q) * SV + dt * 8 + g];
                mma_tf32(o[dt], a, bfr);
            }
        }
        __syncwarp();   // P reads done before next tile overwrites (warp-private)
    }

    // normalize + write (masked query rows -> 0)
    const int rowl = q0 + w16 + g;
    const int rowh = rowl + 8;
    const int qml = mask[b * T_ + rowl];
    const int qmh = mask[b * T_ + rowh];
    const float invl = (qml != 0 && l_lo > 0.0f) ? (1.0f / l_lo) : 0.0f;
    const float invh = (qmh != 0 && l_hi > 0.0f) ? (1.0f / l_hi) : 0.0f;
#pragma unroll
    for (int dt = 0; dt < 8; dt++) {
        const int col = dt * 8 + 2 * q;
        float2 vl = make_float2(o[dt][0] * invl, o[dt][1] * invl);
        float2 vh = make_float2(o[dt][2] * invh, o[dt][3] * invh);
        *(float2*)&y[base + (size_t)rowl * C_ + col] = vl;
        *(float2*)&y[base + (size_t)rowh * C_ + col] = vh;
    }
}

// ---------------------------------------------------------------------------
extern "C" void kernel_launch(void* const* d_in, const int* in_sizes, int n_in,
                              void* d_out, int out_size)
{
    const float* x    = (const float*)d_in[0];
    const float* Wq   = (const float*)d_in[1];
    const float* bq   = (const float*)d_in[2];
    const float* Wk   = (const float*)d_in[3];
    const float* bk   = (const float*)d_in[4];
    const float* Wv   = (const float*)d_in[5];
    const float* bv   = (const float*)d_in[6];
    const int*   mask = (const int*)d_in[7];
    float*       y    = (float*)d_out;

    dim3 ggrid(C_ / 128, M_ / 128, 3);
    qkv_gemm_mma<<<ggrid, 256>>>(x, Wq, bq, Wk, bk, Wv, bv);

    const int att_smem = ATT_SMEM_WORDS * (int)sizeof(uint32_t);
    cudaFuncSetAttribute(attn_mma, cudaFuncAttributeMaxDynamicSharedMemorySize, att_smem);
    dim3 agrid(T_ / 128, B_ * H_);
    attn_mma<<<agrid, 256, att_smem>>>(mask, y);
}